// round 15
// baseline (speedup 1.0000x reference)
#include <cuda_runtime.h>
#include <cuda_bf16.h>

#define N_COLS 4096
#define NT     512
#define M_BKT  2048
#define BPT    (M_BKT / NT)        // 4 buckets owned per thread
#define BKT_W  (1.0f / (float)M_BKT)

#define SH_U   54
#define SH_V   44
#define MASK44 ((1ULL << 44) - 1ULL)
#define VBIAS  (1u << 30)
#define FLAGB  0x80000000u

__device__ float g_row_sums[8192];

static __device__ __forceinline__ int bkt(float x) {
    int b = (int)(x * (float)M_BKT);
    return (b > M_BKT - 1) ? (M_BKT - 1) : b;
}

// one fused atomic: counts + fixed-point weighted sum (order-independent)
static __device__ __forceinline__ void acc_sample(unsigned long long* h, float x, bool isv) {
    const int b = bkt(x);
    const float R = (float)(b + 1) * BKT_W;
    const unsigned int wfix = (unsigned int)((R - x) * 0x1p41f);   // <= 2^30
    unsigned long long add = isv
        ? ((1ULL << SH_V) + (unsigned long long)(VBIAS - wfix))
        : ((1ULL << SH_U) + (unsigned long long)wfix);
    atomicAdd(&h[b], add);
}

__global__ __launch_bounds__(NT, 3)
void w1_row_kernel(const float4* __restrict__ pred,
                   const float4* __restrict__ tru)
{
    __shared__ unsigned long long hist[M_BKT];      // 16 KB fused counters
    __shared__ unsigned int cursor[M_BKT];          // 8 KB offsets | slow flag
    __shared__ unsigned int slab[2 * N_COLS];       // 32 KB (slow buckets only)
    __shared__ unsigned int wsum[16];
    __shared__ float red[16];

    const int row  = blockIdx.x;
    const int t    = threadIdx.x;
    const int lane = t & 31;
    const int wid  = t >> 5;

    #pragma unroll
    for (int j = 0; j < BPT; j++) hist[t * BPT + j] = 0ULL;

    const size_t rbase = (size_t)row * (N_COLS / 4);
    float4 p0 = pred[rbase + t];
    float4 p1 = pred[rbase + t + NT];
    float4 q0 = tru[rbase + t];
    float4 q1 = tru[rbase + t + NT];
    __syncthreads();

    // ---- pass A: one 64-bit atomic per sample ----
    {
        float up[8] = {p0.x, p0.y, p0.z, p0.w, p1.x, p1.y, p1.z, p1.w};
        float vp[8] = {q0.x, q0.y, q0.z, q0.w, q1.x, q1.y, q1.z, q1.w};
        #pragma unroll
        for (int e = 0; e < 8; e++) acc_sample(hist, up[e], false);
        #pragma unroll
        for (int e = 0; e < 8; e++) acc_sample(hist, vp[e], true);
    }
    __syncthreads();

    // ---- packed exclusive scan (u | v<<16) over buckets; extract fsum ----
    unsigned int oB[BPT];
    int          c0[BPT];
    int          cntb[BPT];
    float        fsum[BPT];
    bool         slow[BPT];
    {
        unsigned int run = 0;
        unsigned int eP[BPT];
        #pragma unroll
        for (int j = 0; j < BPT; j++) {
            unsigned long long w = hist[t * BPT + j];
            unsigned int cu = (unsigned int)(w >> SH_U);
            unsigned int cv = (unsigned int)(w >> SH_V) & 0x3FFu;
            long long s64 = (long long)(w & MASK44) - ((long long)cv << 30);
            fsum[j] = (float)s64 * 0x1p-41f;
            cntb[j] = (int)(cu + cv);
            eP[j] = run;
            run += cu | (cv << 16);
        }
        unsigned int inc = run;
        #pragma unroll
        for (int o = 1; o < 32; o <<= 1) {
            unsigned int n2 = __shfl_up_sync(0xffffffffu, inc, o);
            if (lane >= o) inc += n2;
        }
        unsigned int wexc = inc - run;
        if (lane == 31) wsum[wid] = inc;
        __syncthreads();
        if (t < 32) {
            unsigned int v2 = (t < 16) ? wsum[t] : 0u;
            unsigned int i2 = v2;
            #pragma unroll
            for (int o = 1; o < 32; o <<= 1) {
                unsigned int n2 = __shfl_up_sync(0xffffffffu, i2, o);
                if (t >= o) i2 += n2;
            }
            if (t < 16) wsum[t] = i2 - v2;
        }
        __syncthreads();
        const unsigned int base = wsum[wid] + wexc;
        #pragma unroll
        for (int j = 0; j < BPT; j++) {
            unsigned int P  = base + eP[j];
            unsigned int cu = P & 0xFFFFu, cv = P >> 16;
            oB[j] = cu + cv;
            c0[j] = (int)cu - (int)cv;
            const int ac0 = (c0[j] < 0) ? -c0[j] : c0[j];
            slow[j] = (ac0 < cntb[j]);
            cursor[t * BPT + j] = oB[j] | (slow[j] ? FLAGB : 0u);
        }
    }
    __syncthreads();

    // ---- conditional scatter: only samples in slow-flagged buckets ----
    {
        // re-read (L1 hits) to keep register pressure down
        float4 r0 = pred[rbase + t];
        float4 r1 = pred[rbase + t + NT];
        float4 s0 = tru[rbase + t];
        float4 s1 = tru[rbase + t + NT];
        float up[8] = {r0.x, r0.y, r0.z, r0.w, r1.x, r1.y, r1.z, r1.w};
        float vp[8] = {s0.x, s0.y, s0.z, s0.w, s1.x, s1.y, s1.z, s1.w};
        #pragma unroll
        for (int e = 0; e < 8; e++) {
            const int b = bkt(up[e]);
            if (cursor[b] & FLAGB) {
                unsigned int pos = atomicAdd(&cursor[b], 1u) & ~FLAGB;
                slab[pos] = __float_as_uint(up[e]) & ~1u;
            }
        }
        #pragma unroll
        for (int e = 0; e < 8; e++) {
            const int b = bkt(vp[e]);
            if (cursor[b] & FLAGB) {
                unsigned int pos = atomicAdd(&cursor[b], 1u) & ~FLAGB;
                slab[pos] = (__float_as_uint(vp[e]) & ~1u) | 1u;
            }
        }
    }
    __syncthreads();

    // ---- integration ----
    float acc = 0.0f;
    #pragma unroll
    for (int j = 0; j < BPT; j++) {
        if (!slow[j]) {
            // sign-constant: contribution known from fused sum, no slab access
            acc += fabsf((float)c0[j] * BKT_W + fsum[j]);
        } else {
            const int m = t * BPT + j;
            const unsigned int o = oB[j];
            const int cnt = cntb[j];
            // insertion sort slab[o .. o+cnt)
            for (int i2 = 1; i2 < cnt; i2++) {
                unsigned int key = slab[o + i2];
                int j2 = i2 - 1;
                while (j2 >= 0 && slab[o + j2] > key) {
                    slab[o + j2 + 1] = slab[o + j2];
                    j2--;
                }
                slab[o + j2 + 1] = key;
            }
            const float L = (float)m * BKT_W;
            float xp = L;
            int   c  = c0[j];
            for (int s2 = 0; s2 < cnt; s2++) {
                unsigned int k2 = slab[o + s2];
                float x = __uint_as_float(k2 & ~1u);
                acc += fabsf((float)c) * (x - xp);
                c += (k2 & 1u) ? -1 : 1;
                xp = x;
            }
            acc += fabsf((float)c) * (L + BKT_W - xp);
        }
    }

    // ---- block reduction ----
    #pragma unroll
    for (int o = 16; o > 0; o >>= 1)
        acc += __shfl_down_sync(0xffffffffu, acc, o);
    if (lane == 0) red[wid] = acc;
    __syncthreads();
    if (t < 32) {
        float v = (t < 16) ? red[t] : 0.0f;
        #pragma unroll
        for (int o = 8; o > 0; o >>= 1)
            v += __shfl_down_sync(0xffffffffu, v, o);
        if (t == 0) g_row_sums[row] = v;
    }
}

// Deterministic final reduction: single block, fixed iteration order.
__global__ void w1_reduce_kernel(float* __restrict__ out, int B)
{
    __shared__ float red[32];
    float local = 0.0f;
    for (int i = threadIdx.x; i < B; i += 1024)
        local += g_row_sums[i];
    #pragma unroll
    for (int o = 16; o > 0; o >>= 1)
        local += __shfl_down_sync(0xffffffffu, local, o);
    if ((threadIdx.x & 31) == 0) red[threadIdx.x >> 5] = local;
    __syncthreads();
    if (threadIdx.x < 32) {
        float v = red[threadIdx.x];
        #pragma unroll
        for (int o = 16; o > 0; o >>= 1)
            v += __shfl_down_sync(0xffffffffu, v, o);
        if (threadIdx.x == 0)
            out[0] = v / ((float)N_COLS * (float)B);
    }
}

extern "C" void kernel_launch(void* const* d_in, const int* in_sizes, int n_in,
                              void* d_out, int out_size)
{
    const float4* pred = (const float4*)d_in[0];
    const float4* tru  = (const float4*)d_in[1];
    float* out = (float*)d_out;

    const int B = in_sizes[0] / N_COLS;  // 4096

    w1_row_kernel<<<B, NT>>>(pred, tru);
    w1_reduce_kernel<<<1, 1024>>>(out, B);
}

// round 17
// speedup vs baseline: 1.0004x; 1.0004x over previous
#include <cuda_runtime.h>
#include <cuda_bf16.h>

#define N_COLS 4096
#define NT     512
#define M_BKT  2048
#define BPT    (M_BKT / NT)        // 4 buckets owned per thread
#define BKT_W  (1.0f / (float)M_BKT)

__device__ float g_row_sums[8192];

static __device__ __forceinline__ int bkt(float x) {
    int b = (int)(x * (float)M_BKT);
    return (b > M_BKT - 1) ? (M_BKT - 1) : ((b < 0) ? 0 : b);
}

static __device__ __forceinline__ void ceu(unsigned int& x, unsigned int& y) {
    unsigned int lo = umin(x, y);
    y = umax(x, y);
    x = lo;
}

__global__ __launch_bounds__(NT, 3)
void w1_row_kernel(const float4* __restrict__ pred,
                   const float4* __restrict__ tru)
{
    // counts (packed u|v<<16) -> combined offsets -> scatter cursors
    __shared__ unsigned int cursor[M_BKT];          // 8 KB
    __shared__ unsigned int slab[2 * N_COLS];       // 32 KB: bucketed keys
    __shared__ unsigned int wsum[16];
    __shared__ float red[16];

    const int row  = blockIdx.x;
    const int t    = threadIdx.x;
    const int lane = t & 31;
    const int wid  = t >> 5;

    // zero own counters
    #pragma unroll
    for (int j = 0; j < BPT; j++) cursor[t * BPT + j] = 0u;

    const size_t rbase = (size_t)row * (N_COLS / 4);
    float4 p0 = pred[rbase + t];
    float4 p1 = pred[rbase + t + NT];
    float4 q0 = tru[rbase + t];
    float4 q1 = tru[rbase + t + NT];
    __syncthreads();   // counters zeroed before atomics

    // ---- histogram: u -> +1 (low half), v -> +1<<16 (high half) ----
    {
        float up[8] = {p0.x, p0.y, p0.z, p0.w, p1.x, p1.y, p1.z, p1.w};
        float vp[8] = {q0.x, q0.y, q0.z, q0.w, q1.x, q1.y, q1.z, q1.w};
        #pragma unroll
        for (int e = 0; e < 8; e++) atomicAdd(&cursor[bkt(up[e])], 1u);
        #pragma unroll
        for (int e = 0; e < 8; e++) atomicAdd(&cursor[bkt(vp[e])], 0x10000u);
    }
    __syncthreads();

    // ---- packed exclusive scan over M_BKT buckets (thread owns BPT contiguous) ----
    unsigned int eP[BPT];     // packed exclusive prefix within thread
    unsigned int oB[BPT];     // combined slab offset per owned bucket
    int          c0[BPT];     // cumU - cumV entering the bucket
    {
        unsigned int run = 0;
        unsigned int h[BPT];
        #pragma unroll
        for (int j = 0; j < BPT; j++) {
            h[j]  = cursor[t * BPT + j];
            eP[j] = run;
            run  += h[j];
        }
        // warp inclusive scan of run
        unsigned int inc = run;
        #pragma unroll
        for (int o = 1; o < 32; o <<= 1) {
            unsigned int n2 = __shfl_up_sync(0xffffffffu, inc, o);
            if (lane >= o) inc += n2;
        }
        unsigned int wexc = inc - run;
        if (lane == 31) wsum[wid] = inc;
        __syncthreads();
        if (t < 32) {
            unsigned int v2 = (t < 16) ? wsum[t] : 0u;
            unsigned int i2 = v2;
            #pragma unroll
            for (int o = 1; o < 32; o <<= 1) {
                unsigned int n2 = __shfl_up_sync(0xffffffffu, i2, o);
                if (t >= o) i2 += n2;
            }
            if (t < 16) wsum[t] = i2 - v2;   // exclusive warp base
        }
        __syncthreads();
        const unsigned int base = wsum[wid] + wexc;
        #pragma unroll
        for (int j = 0; j < BPT; j++) {
            unsigned int P = base + eP[j];               // packed cumU | cumV<<16
            unsigned int cu = P & 0xFFFFu, cv = P >> 16;
            oB[j] = cu + cv;
            c0[j] = (int)cu - (int)cv;
            cursor[t * BPT + j] = oB[j];                 // own bucket: safe rewrite
        }
    }
    __syncthreads();

    // ---- scatter keys: key = (bits & ~1) | tag  (tag: u=0, v=1) ----
    {
        float up[8] = {p0.x, p0.y, p0.z, p0.w, p1.x, p1.y, p1.z, p1.w};
        float vp[8] = {q0.x, q0.y, q0.z, q0.w, q1.x, q1.y, q1.z, q1.w};
        #pragma unroll
        for (int e = 0; e < 8; e++) {
            unsigned int pos = atomicAdd(&cursor[bkt(up[e])], 1u);
            slab[pos] = __float_as_uint(up[e]) & ~1u;
        }
        #pragma unroll
        for (int e = 0; e < 8; e++) {
            unsigned int pos = atomicAdd(&cursor[bkt(vp[e])], 1u);
            slab[pos] = (__float_as_uint(vp[e]) & ~1u) | 1u;
        }
    }
    __syncthreads();

    // ---- per-bucket integration of |cumU - cumV| ----
    float acc = 0.0f;
    #pragma unroll
    for (int j = 0; j < BPT; j++) {
        const int m   = t * BPT + j;
        const unsigned int o = oB[j];
        const int cnt = (int)(cursor[m] - o);
        const float L = (float)m * BKT_W;
        const float R = L + BKT_W;
        const int ac0 = (c0[j] < 0) ? -c0[j] : c0[j];

        if (ac0 >= cnt) {
            // Sign-constant fast path: integral = |c0*W + sum s_i*(R - x_i)|,
            // order-free — no sort, no walk.
            float s = (float)c0[j] * BKT_W;
            for (int i2 = 0; i2 < cnt; i2++) {
                unsigned int k2 = slab[o + i2];
                float x = __uint_as_float(k2 & ~1u);
                float w = R - x;
                s += (k2 & 1u) ? -w : w;
            }
            acc += fabsf(s);
        } else if (cnt <= 12) {
            // Slow path, register edition: independent LDS loads (INF-padded),
            // branchless 12-element odd-even transposition network, branchless walk.
            unsigned int k[12];
            #pragma unroll
            for (int r = 0; r < 12; r++)
                k[r] = (r < cnt) ? slab[o + r] : 0xFFFFFFFFu;

            #pragma unroll
            for (int rr = 0; rr < 6; rr++) {
                ceu(k[0], k[1]); ceu(k[2], k[3]); ceu(k[4], k[5]);
                ceu(k[6], k[7]); ceu(k[8], k[9]); ceu(k[10], k[11]);
                ceu(k[1], k[2]); ceu(k[3], k[4]); ceu(k[5], k[6]);
                ceu(k[7], k[8]); ceu(k[9], k[10]);
            }

            // walk: pads clamp to R -> zero-width segments; counter corruption
            // after the first pad only touches zero-width terms.
            float xp = L;
            float cf = (float)c0[j];
            #pragma unroll
            for (int r = 0; r < 12; r++) {
                float x = fminf(__uint_as_float(k[r] & ~1u), R);
                acc += fabsf(cf) * (x - xp);
                cf += (k[r] & 1u) ? -1.0f : 1.0f;
                xp = x;
            }
            acc += fabsf(cf) * (R - xp);
        } else {
            // Rare fallback (cnt > 12): smem insertion sort + walk.
            for (int i2 = 1; i2 < cnt; i2++) {
                unsigned int key = slab[o + i2];
                int j2 = i2 - 1;
                while (j2 >= 0 && slab[o + j2] > key) {
                    slab[o + j2 + 1] = slab[o + j2];
                    j2--;
                }
                slab[o + j2 + 1] = key;
            }
            float xp = L;
            int   c  = c0[j];
            for (int s2 = 0; s2 < cnt; s2++) {
                unsigned int k2 = slab[o + s2];
                float x = __uint_as_float(k2 & ~1u);
                acc += fabsf((float)c) * (x - xp);
                c += (k2 & 1u) ? -1 : 1;
                xp = x;
            }
            acc += fabsf((float)c) * (R - xp);
        }
    }

    // ---- block reduction -> g_row_sums[row] ----
    #pragma unroll
    for (int o = 16; o > 0; o >>= 1)
        acc += __shfl_down_sync(0xffffffffu, acc, o);
    if (lane == 0) red[wid] = acc;
    __syncthreads();
    if (t < 32) {
        float v = (t < 16) ? red[t] : 0.0f;
        #pragma unroll
        for (int o = 8; o > 0; o >>= 1)
            v += __shfl_down_sync(0xffffffffu, v, o);
        if (t == 0) g_row_sums[row] = v;
    }
}

// Deterministic final reduction: single block, fixed iteration order.
__global__ void w1_reduce_kernel(float* __restrict__ out, int B)
{
    __shared__ float red[32];
    float local = 0.0f;
    for (int i = threadIdx.x; i < B; i += 1024)
        local += g_row_sums[i];
    #pragma unroll
    for (int o = 16; o > 0; o >>= 1)
        local += __shfl_down_sync(0xffffffffu, local, o);
    if ((threadIdx.x & 31) == 0) red[threadIdx.x >> 5] = local;
    __syncthreads();
    if (threadIdx.x < 32) {
        float v = red[threadIdx.x];
        #pragma unroll
        for (int o = 16; o > 0; o >>= 1)
            v += __shfl_down_sync(0xffffffffu, v, o);
        if (threadIdx.x == 0)
            out[0] = v / ((float)N_COLS * (float)B);
    }
}

extern "C" void kernel_launch(void* const* d_in, const int* in_sizes, int n_in,
                              void* d_out, int out_size)
{
    const float4* pred = (const float4*)d_in[0];
    const float4* tru  = (const float4*)d_in[1];
    float* out = (float*)d_out;

    const int B = in_sizes[0] / N_COLS;  // 4096

    w1_row_kernel<<<B, NT>>>(pred, tru);
    w1_reduce_kernel<<<1, 1024>>>(out, B);
}